// round 12
// baseline (speedup 1.0000x reference)
#include <cuda_runtime.h>
#include <cstdint>

#define ALPHA 26
#define TPB   256
#define WARPS (TPB / 32)                 // 8 warps per block
#define CHUNK_TOK    64                  // tokens per warp-chunk (2 per lane)
#define CHUNK_FLOATS (CHUNK_TOK * ALPHA) // 1664
#define CHUNK_BYTES  (CHUNK_FLOATS * 4)  // 6656 (16B multiple)
#define SEQ   8192
#define GRID  296                        // 2 blocks/SM * 148 SMs
#define TW    (GRID * WARPS)             // 2368 warp pipelines

__constant__ float c_rot[ALPHA * ALPHA]; // NORMALIZED rotor, row-major
__device__ float   g_rn[ALPHA * ALPHA];  // staging for normalized rotor

__device__ __forceinline__ uint32_t smem_u32(const void* p) {
    return (uint32_t)__cvta_generic_to_shared(p);
}
__device__ __forceinline__ void mbar_init(uint32_t mbar, uint32_t cnt) {
    asm volatile("mbarrier.init.shared.b64 [%0], %1;" :: "r"(mbar), "r"(cnt) : "memory");
}
__device__ __forceinline__ void mbar_expect_tx(uint32_t mbar, uint32_t bytes) {
    asm volatile("mbarrier.arrive.expect_tx.shared.b64 _, [%0], %1;"
                 :: "r"(mbar), "r"(bytes) : "memory");
}
__device__ __forceinline__ void mbar_wait(uint32_t mbar, uint32_t parity) {
    asm volatile(
        "{\n\t.reg .pred P;\n\t"
        "WAIT_%=:\n\t"
        "mbarrier.try_wait.parity.acquire.cta.shared::cta.b64 P, [%0], %1, 0x989680;\n\t"
        "@P bra.uni DONE_%=;\n\t"
        "bra.uni WAIT_%=;\n\t"
        "DONE_%=:\n\t}"
        :: "r"(mbar), "r"(parity) : "memory");
}
__device__ __forceinline__ void bulk_load(uint32_t sdst, const void* gsrc,
                                          uint32_t bytes, uint32_t mbar) {
    asm volatile(
        "cp.async.bulk.shared::cta.global.mbarrier::complete_tx::bytes [%0], [%1], %2, [%3];"
        :: "r"(sdst), "l"(gsrc), "r"(bytes), "r"(mbar) : "memory");
}
__device__ __forceinline__ void bulk_store(void* gdst, uint32_t ssrc, uint32_t bytes) {
    asm volatile("cp.async.bulk.global.shared::cta.bulk_group [%0], [%1], %2;"
                 :: "l"(gdst), "r"(ssrc), "r"(bytes) : "memory");
}
__device__ __forceinline__ void bulk_commit()    { asm volatile("cp.async.bulk.commit_group;" ::: "memory"); }
__device__ __forceinline__ void bulk_wait_read() { asm volatile("cp.async.bulk.wait_group.read 0;" ::: "memory"); }
__device__ __forceinline__ void bulk_wait_all()  { asm volatile("cp.async.bulk.wait_group 0;" ::: "memory"); }
__device__ __forceinline__ void fence_async()    { asm volatile("fence.proxy.async.shared::cta;" ::: "memory"); }

// --- tiny setup kernel: L2-normalize rotor rows into g_rn ---
__global__ void norm_rotor_kernel(const float* __restrict__ rotor) {
    int r = threadIdx.x;
    if (r < ALPHA) {
        float ss = 0.f;
        #pragma unroll
        for (int j = 0; j < ALPHA; ++j) {
            float v = rotor[r * ALPHA + j];
            ss = fmaf(v, v, ss);
        }
        float inv = rsqrtf(ss);
        #pragma unroll
        for (int j = 0; j < ALPHA; ++j)
            g_rn[r * ALPHA + j] = rotor[r * ALPHA + j] * inv;
    }
}

__global__ __launch_bounds__(TPB, 2)
void rotor_kernel(const float* __restrict__ x,
                  float* __restrict__ out, int nChunks)
{
    extern __shared__ __align__(128) float s_dyn[];   // WARPS * 2 * CHUNK_FLOATS
    __shared__ __align__(8) unsigned long long s_mbar[WARPS * 2];

    const int tid  = threadIdx.x;
    const int wid  = tid >> 5;
    const int lane = tid & 31;

    if (tid < WARPS * 2) mbar_init(smem_u32(&s_mbar[tid]), 1);
    __syncthreads();   // mbarrier init visible to all warps

    // per-warp resources
    float* __restrict__ wbuf = s_dyn + wid * 2 * CHUNK_FLOATS;
    const uint32_t wb  = smem_u32(wbuf);
    const uint32_t mbA = smem_u32(&s_mbar[wid * 2 + 0]);
    const uint32_t mbB = smem_u32(&s_mbar[wid * 2 + 1]);

    const int c0 = blockIdx.x * WARPS + wid;   // this warp's first chunk

    // --- prologue: prefetch first two chunks (lane 0 only) ---
    if (lane == 0) {
        if (c0 < nChunks) {
            mbar_expect_tx(mbA, CHUNK_BYTES);
            bulk_load(wb, x + (size_t)c0 * CHUNK_FLOATS, CHUNK_BYTES, mbA);
        }
        if (c0 + TW < nChunks) {
            mbar_expect_tx(mbB, CHUNK_BYTES);
            bulk_load(wb + CHUNK_BYTES, x + (size_t)(c0 + TW) * CHUNK_FLOATS,
                      CHUNK_BYTES, mbB);
        }
    }

    int k = 0;
    for (int c = c0; c < nChunks; c += TW, ++k) {
        const int b  = k & 1;
        const int ph = (k >> 1) & 1;
        mbar_wait(b ? mbB : mbA, ph);

        float* __restrict__ sb = wbuf + b * CHUNK_FLOATS;

        // --- two tokens per lane ---
        const int tok0 = c * CHUNK_TOK + lane;
        const int tok1 = tok0 + 32;
        const int shift0 = (tok0 & (SEQ - 1)) % ALPHA;
        const int shift1 = (tok1 & (SEQ - 1)) % ALPHA;
        const float* __restrict__ xr0 = sb + lane * ALPHA;
        const float* __restrict__ xr1 = sb + (lane + 32) * ALPHA;

        unsigned long long acc0[13], acc1[13];
        #pragma unroll
        for (int p = 0; p < 13; ++p) { acc0[p] = 0ull; acc1[p] = 0ull; }

        #pragma unroll
        for (int r = 0; r < ALPHA; ++r) {
            int i0 = r - shift0; i0 += (i0 >> 31) & ALPHA;
            int i1 = r - shift1; i1 += (i1 >> 31) & ALPHA;
            float xv0 = xr0[i0];
            float xv1 = xr1[i1];
            unsigned long long xx0, xx1;
            asm("mov.b64 %0, {%1, %1};" : "=l"(xx0) : "f"(xv0));
            asm("mov.b64 %0, {%1, %1};" : "=l"(xx1) : "f"(xv1));

            // normalized rotor row r from CONSTANT memory: 13 x 8B, imm offsets
            #pragma unroll
            for (int p = 0; p < 13; ++p) {
                float2 f = *(const float2*)(c_rot + r * ALPHA + 2 * p);
                unsigned long long bb;
                asm("mov.b64 %0, {%1, %2};" : "=l"(bb) : "f"(f.x), "f"(f.y));
                asm("fma.rn.f32x2 %0, %1, %2, %0;" : "+l"(acc0[p]) : "l"(bb), "l"(xx0));
                asm("fma.rn.f32x2 %0, %1, %2, %0;" : "+l"(acc1[p]) : "l"(bb), "l"(xx1));
            }
        }

        // --- softmax (no max-subtract: logits are N(0,1), |logit| < ~7) ---
        float e0[ALPHA], e1[ALPHA];
        #pragma unroll
        for (int p = 0; p < 13; ++p) {
            float a, bvf, cvf, d;
            asm("mov.b64 {%0, %1}, %2;" : "=f"(a), "=f"(bvf) : "l"(acc0[p]));
            asm("mov.b64 {%0, %1}, %2;" : "=f"(cvf), "=f"(d) : "l"(acc1[p]));
            e0[2*p] = __expf(a);  e0[2*p+1] = __expf(bvf);
            e1[2*p] = __expf(cvf); e1[2*p+1] = __expf(d);
        }
        // tree sums (depth ~5)
        float t0[13], t1[13];
        #pragma unroll
        for (int p = 0; p < 13; ++p) { t0[p] = e0[2*p] + e0[2*p+1]; t1[p] = e1[2*p] + e1[2*p+1]; }
        float s0a = (t0[0] + t0[1]) + (t0[2] + t0[3]);
        float s0b = (t0[4] + t0[5]) + (t0[6] + t0[7]);
        float s0c = (t0[8] + t0[9]) + (t0[10] + t0[11]);
        float sm0 = (s0a + s0b) + (s0c + t0[12]);
        float s1a = (t1[0] + t1[1]) + (t1[2] + t1[3]);
        float s1b = (t1[4] + t1[5]) + (t1[6] + t1[7]);
        float s1c = (t1[8] + t1[9]) + (t1[10] + t1[11]);
        float sm1 = (s1a + s1b) + (s1c + t1[12]);

        const float in0 = __fdividef(1.0f, sm0);
        const float in1 = __fdividef(1.0f, sm1);
        unsigned long long iv0, iv1;
        asm("mov.b64 %0, {%1, %1};" : "=l"(iv0) : "f"(in0));
        asm("mov.b64 %0, {%1, %1};" : "=l"(iv1) : "f"(in1));

        // packed scale + 8B shared stores into own rows of sb
        unsigned long long* w0 = (unsigned long long*)(sb + lane * ALPHA);
        unsigned long long* w1 = (unsigned long long*)(sb + (lane + 32) * ALPHA);
        #pragma unroll
        for (int p = 0; p < 13; ++p) {
            unsigned long long p0, p1, r0, r1;
            asm("mov.b64 %0, {%1, %2};" : "=l"(p0) : "f"(e0[2*p]), "f"(e0[2*p+1]));
            asm("mov.b64 %0, {%1, %2};" : "=l"(p1) : "f"(e1[2*p]), "f"(e1[2*p+1]));
            asm("mul.rn.f32x2 %0, %1, %2;" : "=l"(r0) : "l"(p0), "l"(iv0));
            asm("mul.rn.f32x2 %0, %1, %2;" : "=l"(r1) : "l"(p1), "l"(iv1));
            w0[p] = r0;
            w1[p] = r1;
        }
        __syncwarp();                                // warp's STS all done

        if (lane == 0) {
            fence_async();                           // STS visible to async proxy
            bulk_store(out + (size_t)c * CHUNK_FLOATS, wb + b * CHUNK_BYTES, CHUNK_BYTES);
            bulk_commit();
            const int cn = c + 2 * TW;
            if (cn < nChunks) {
                bulk_wait_read();                    // this buffer's store reads drained
                mbar_expect_tx(b ? mbB : mbA, CHUNK_BYTES);
                bulk_load(wb + b * CHUNK_BYTES, x + (size_t)cn * CHUNK_FLOATS,
                          CHUNK_BYTES, b ? mbB : mbA);
            }
        }
        // lanes 1..31 run ahead to next chunk's mbar_wait (other buffer) — safe
    }

    if (lane == 0) bulk_wait_all();                  // gmem stores complete before exit
}

extern "C" void kernel_launch(void* const* d_in, const int* in_sizes, int n_in,
                              void* d_out, int out_size)
{
    const float* x     = (const float*)d_in[0];   // [128, 8192, 26] f32
    const float* rotor = (const float*)d_in[1];   // [26, 26] f32
    float* out         = (float*)d_out;

    const int total_tokens = out_size / ALPHA;    // 1,048,576
    const int nChunks = total_tokens / CHUNK_TOK; // 16384

    // 1) normalize rotor rows into device staging
    norm_rotor_kernel<<<1, 32>>>(rotor);
    // 2) staging -> constant bank (D2D async memcpy node; graph-capturable)
    void* g_rn_addr = nullptr;
    cudaGetSymbolAddress(&g_rn_addr, g_rn);
    cudaMemcpyToSymbolAsync(c_rot, g_rn_addr, ALPHA * ALPHA * sizeof(float), 0,
                            cudaMemcpyDeviceToDevice, 0);

    const int dyn_smem = WARPS * 2 * CHUNK_BYTES; // 106496 B
    cudaFuncSetAttribute(rotor_kernel,
                         cudaFuncAttributeMaxDynamicSharedMemorySize, dyn_smem);

    rotor_kernel<<<GRID, TPB, dyn_smem>>>(x, out, nChunks);
}

// round 13
// speedup vs baseline: 1.0442x; 1.0442x over previous
#include <cuda_runtime.h>
#include <cstdint>

#define ALPHA 26
#define TPB   256
#define WARPS (TPB / 32)                 // 8 warps per block
#define CHUNK_TOK    64                  // tokens per warp-chunk (2 per lane)
#define CHUNK_FLOATS (CHUNK_TOK * ALPHA) // 1664
#define CHUNK_BYTES  (CHUNK_FLOATS * 4)  // 6656 (16B multiple)
#define SEQ   8192
#define GRID  296                        // 2 blocks/SM * 148 SMs
#define TW    (GRID * WARPS)             // 2368 warp pipelines

__device__ __forceinline__ uint32_t smem_u32(const void* p) {
    return (uint32_t)__cvta_generic_to_shared(p);
}
__device__ __forceinline__ void mbar_init(uint32_t mbar, uint32_t cnt) {
    asm volatile("mbarrier.init.shared.b64 [%0], %1;" :: "r"(mbar), "r"(cnt) : "memory");
}
__device__ __forceinline__ void mbar_expect_tx(uint32_t mbar, uint32_t bytes) {
    asm volatile("mbarrier.arrive.expect_tx.shared.b64 _, [%0], %1;"
                 :: "r"(mbar), "r"(bytes) : "memory");
}
__device__ __forceinline__ void mbar_wait(uint32_t mbar, uint32_t parity) {
    asm volatile(
        "{\n\t.reg .pred P;\n\t"
        "WAIT_%=:\n\t"
        "mbarrier.try_wait.parity.acquire.cta.shared::cta.b64 P, [%0], %1, 0x989680;\n\t"
        "@P bra.uni DONE_%=;\n\t"
        "bra.uni WAIT_%=;\n\t"
        "DONE_%=:\n\t}"
        :: "r"(mbar), "r"(parity) : "memory");
}
__device__ __forceinline__ void bulk_load(uint32_t sdst, const void* gsrc,
                                          uint32_t bytes, uint32_t mbar) {
    asm volatile(
        "cp.async.bulk.shared::cta.global.mbarrier::complete_tx::bytes [%0], [%1], %2, [%3];"
        :: "r"(sdst), "l"(gsrc), "r"(bytes), "r"(mbar) : "memory");
}
__device__ __forceinline__ void bulk_store(void* gdst, uint32_t ssrc, uint32_t bytes) {
    asm volatile("cp.async.bulk.global.shared::cta.bulk_group [%0], [%1], %2;"
                 :: "l"(gdst), "r"(ssrc), "r"(bytes) : "memory");
}
__device__ __forceinline__ void bulk_commit()    { asm volatile("cp.async.bulk.commit_group;" ::: "memory"); }
__device__ __forceinline__ void bulk_wait_read() { asm volatile("cp.async.bulk.wait_group.read 0;" ::: "memory"); }
__device__ __forceinline__ void bulk_wait_all()  { asm volatile("cp.async.bulk.wait_group 0;" ::: "memory"); }
__device__ __forceinline__ void fence_async()    { asm volatile("fence.proxy.async.shared::cta;" ::: "memory"); }

__global__ __launch_bounds__(TPB, 2)
void rotor_kernel(const float* __restrict__ x,
                  const float* __restrict__ rotor,
                  float* __restrict__ out, int nChunks)
{
    extern __shared__ __align__(128) float s_dyn[];     // WARPS * 2 * CHUNK_FLOATS
    __shared__ __align__(16) float s_rn[ALPHA][ALPHA + 2]; // normalized rotor, padded rows
    __shared__ float s_inv[ALPHA];
    __shared__ __align__(8) unsigned long long s_mbar[WARPS * 2];

    const int tid  = threadIdx.x;
    const int wid  = tid >> 5;
    const int lane = tid & 31;

    // --- normalize rotor rows into smem (once per persistent block) ---
    if (tid < ALPHA) {
        float ss = 0.f;
        #pragma unroll
        for (int j = 0; j < ALPHA; ++j) {
            float v = rotor[tid * ALPHA + j];
            ss = fmaf(v, v, ss);
        }
        s_inv[tid] = rsqrtf(ss);
    }
    if (tid < WARPS * 2) mbar_init(smem_u32(&s_mbar[tid]), 1);
    __syncthreads();
    for (int e = tid; e < ALPHA * ALPHA; e += TPB) {
        int r = e / ALPHA;
        s_rn[r][e - r * ALPHA] = rotor[e] * s_inv[r];
    }
    __syncthreads();   // rn + mbarrier init visible to all warps

    // per-warp resources
    float* __restrict__ wbuf = s_dyn + wid * 2 * CHUNK_FLOATS;
    const uint32_t wb  = smem_u32(wbuf);
    const uint32_t mbA = smem_u32(&s_mbar[wid * 2 + 0]);
    const uint32_t mbB = smem_u32(&s_mbar[wid * 2 + 1]);

    const int c0 = blockIdx.x * WARPS + wid;   // this warp's first chunk

    // --- prologue: prefetch first two chunks (lane 0 only) ---
    if (lane == 0) {
        if (c0 < nChunks) {
            mbar_expect_tx(mbA, CHUNK_BYTES);
            bulk_load(wb, x + (size_t)c0 * CHUNK_FLOATS, CHUNK_BYTES, mbA);
        }
        if (c0 + TW < nChunks) {
            mbar_expect_tx(mbB, CHUNK_BYTES);
            bulk_load(wb + CHUNK_BYTES, x + (size_t)(c0 + TW) * CHUNK_FLOATS,
                      CHUNK_BYTES, mbB);
        }
    }

    int k = 0;
    for (int c = c0; c < nChunks; c += TW, ++k) {
        const int b  = k & 1;
        const int ph = (k >> 1) & 1;
        mbar_wait(b ? mbB : mbA, ph);

        float* __restrict__ sb = wbuf + b * CHUNK_FLOATS;

        // --- two tokens per lane ---
        const int tok0 = c * CHUNK_TOK + lane;
        const int tok1 = tok0 + 32;
        const int shift0 = (tok0 & (SEQ - 1)) % ALPHA;
        const int shift1 = (tok1 & (SEQ - 1)) % ALPHA;
        const float* __restrict__ xr0 = sb + lane * ALPHA;
        const float* __restrict__ xr1 = sb + (lane + 32) * ALPHA;

        unsigned long long acc0[13], acc1[13];
        #pragma unroll
        for (int p = 0; p < 13; ++p) { acc0[p] = 0ull; acc1[p] = 0ull; }

        #pragma unroll
        for (int r = 0; r < ALPHA; ++r) {
            int i0 = r - shift0; i0 += (i0 >> 31) & ALPHA;
            int i1 = r - shift1; i1 += (i1 >> 31) & ALPHA;
            float xv0 = xr0[i0];
            float xv1 = xr1[i1];
            unsigned long long xx0, xx1;
            asm("mov.b64 %0, {%1, %1};" : "=l"(xx0) : "f"(xv0));
            asm("mov.b64 %0, {%1, %1};" : "=l"(xx1) : "f"(xv1));

            // rn row r: 6 x LDS.128 + 1 x LDS.64, all warp-uniform broadcast
            const float4* __restrict__ rr4 = (const float4*)(&s_rn[r][0]);
            #pragma unroll
            for (int cc = 0; cc < 6; ++cc) {
                float4 f = rr4[cc];
                unsigned long long b01, b23;
                asm("mov.b64 %0, {%1, %2};" : "=l"(b01) : "f"(f.x), "f"(f.y));
                asm("mov.b64 %0, {%1, %2};" : "=l"(b23) : "f"(f.z), "f"(f.w));
                asm("fma.rn.f32x2 %0, %1, %2, %0;" : "+l"(acc0[2*cc  ]) : "l"(b01), "l"(xx0));
                asm("fma.rn.f32x2 %0, %1, %2, %0;" : "+l"(acc0[2*cc+1]) : "l"(b23), "l"(xx0));
                asm("fma.rn.f32x2 %0, %1, %2, %0;" : "+l"(acc1[2*cc  ]) : "l"(b01), "l"(xx1));
                asm("fma.rn.f32x2 %0, %1, %2, %0;" : "+l"(acc1[2*cc+1]) : "l"(b23), "l"(xx1));
            }
            {
                float2 f = *(const float2*)(&s_rn[r][24]);
                unsigned long long bb;
                asm("mov.b64 %0, {%1, %2};" : "=l"(bb) : "f"(f.x), "f"(f.y));
                asm("fma.rn.f32x2 %0, %1, %2, %0;" : "+l"(acc0[12]) : "l"(bb), "l"(xx0));
                asm("fma.rn.f32x2 %0, %1, %2, %0;" : "+l"(acc1[12]) : "l"(bb), "l"(xx1));
            }
        }

        // --- softmax (no max-subtract: rows are unit-norm, x ~ N(0,1), |logit| < ~7) ---
        float e0[ALPHA], e1[ALPHA];
        #pragma unroll
        for (int p = 0; p < 13; ++p) {
            float a, bvf, cvf, d;
            asm("mov.b64 {%0, %1}, %2;" : "=f"(a), "=f"(bvf) : "l"(acc0[p]));
            asm("mov.b64 {%0, %1}, %2;" : "=f"(cvf), "=f"(d) : "l"(acc1[p]));
            e0[2*p] = __expf(a);   e0[2*p+1] = __expf(bvf);
            e1[2*p] = __expf(cvf); e1[2*p+1] = __expf(d);
        }
        // tree sums (depth ~5)
        float t0[13], t1[13];
        #pragma unroll
        for (int p = 0; p < 13; ++p) { t0[p] = e0[2*p] + e0[2*p+1]; t1[p] = e1[2*p] + e1[2*p+1]; }
        float s0a = (t0[0] + t0[1]) + (t0[2] + t0[3]);
        float s0b = (t0[4] + t0[5]) + (t0[6] + t0[7]);
        float s0c = (t0[8] + t0[9]) + (t0[10] + t0[11]);
        float sm0 = (s0a + s0b) + (s0c + t0[12]);
        float s1a = (t1[0] + t1[1]) + (t1[2] + t1[3]);
        float s1b = (t1[4] + t1[5]) + (t1[6] + t1[7]);
        float s1c = (t1[8] + t1[9]) + (t1[10] + t1[11]);
        float sm1 = (s1a + s1b) + (s1c + t1[12]);

        const float in0 = __fdividef(1.0f, sm0);
        const float in1 = __fdividef(1.0f, sm1);
        unsigned long long iv0, iv1;
        asm("mov.b64 %0, {%1, %1};" : "=l"(iv0) : "f"(in0));
        asm("mov.b64 %0, {%1, %1};" : "=l"(iv1) : "f"(in1));

        // packed scale + 8B shared stores into own rows of sb
        unsigned long long* w0 = (unsigned long long*)(sb + lane * ALPHA);
        unsigned long long* w1 = (unsigned long long*)(sb + (lane + 32) * ALPHA);
        #pragma unroll
        for (int p = 0; p < 13; ++p) {
            unsigned long long p0, p1, r0, r1;
            asm("mov.b64 %0, {%1, %2};" : "=l"(p0) : "f"(e0[2*p]), "f"(e0[2*p+1]));
            asm("mov.b64 %0, {%1, %2};" : "=l"(p1) : "f"(e1[2*p]), "f"(e1[2*p+1]));
            asm("mul.rn.f32x2 %0, %1, %2;" : "=l"(r0) : "l"(p0), "l"(iv0));
            asm("mul.rn.f32x2 %0, %1, %2;" : "=l"(r1) : "l"(p1), "l"(iv1));
            w0[p] = r0;
            w1[p] = r1;
        }
        __syncwarp();                                // warp's STS all done

        if (lane == 0) {
            fence_async();                           // STS visible to async proxy
            bulk_store(out + (size_t)c * CHUNK_FLOATS, wb + b * CHUNK_BYTES, CHUNK_BYTES);
            bulk_commit();
            const int cn = c + 2 * TW;
            if (cn < nChunks) {
                bulk_wait_read();                    // this buffer's store reads drained
                mbar_expect_tx(b ? mbB : mbA, CHUNK_BYTES);
                bulk_load(wb + b * CHUNK_BYTES, x + (size_t)cn * CHUNK_FLOATS,
                          CHUNK_BYTES, b ? mbB : mbA);
            }
        }
        // lanes 1..31 run ahead to next chunk's mbar_wait (other buffer) — safe
    }

    if (lane == 0) bulk_wait_all();                  // gmem stores complete before exit
}

extern "C" void kernel_launch(void* const* d_in, const int* in_sizes, int n_in,
                              void* d_out, int out_size)
{
    const float* x     = (const float*)d_in[0];   // [128, 8192, 26] f32
    const float* rotor = (const float*)d_in[1];   // [26, 26] f32
    float* out         = (float*)d_out;

    const int total_tokens = out_size / ALPHA;    // 1,048,576
    const int nChunks = total_tokens / CHUNK_TOK; // 16384

    const int dyn_smem = WARPS * 2 * CHUNK_BYTES; // 106496 B
    cudaFuncSetAttribute(rotor_kernel,
                         cudaFuncAttributeMaxDynamicSharedMemorySize, dyn_smem);

    rotor_kernel<<<GRID, TPB, dyn_smem>>>(x, rotor, out, nChunks);
}